// round 1
// baseline (speedup 1.0000x reference)
#include <cuda_runtime.h>
#include <cstdint>
#include <cstring>

// ---------------------------------------------------------------------------
// GraphSAGE (2-layer, mean aggregator) + graph-mean readout + linear classifier
// Inputs (metadata order):
//  0 h[100000,128] f32      1 perm[64,128] f32    2 src[1.6M] i32
//  3 dst[1.6M] i32          4 graph_ids[100000] i32 (sorted)
//  5 W1_self[128,128]       6 W1_neigh[128,128]   7 b1[128]
//  8 W2_self[128,128]       9 W2_neigh[128,128]  10 b2[128]
// 11 Wc[256,8]             12 bc[8]
// Output: [64,8] f32
// ---------------------------------------------------------------------------

#define K_NODES  100000
#define K_EDGES  1600000
#define K_GRAPHS 64
#define K_DIM    128
#define K_CLS    8
#define K_NB     98            // ceil(100000/1024)

// scratch (static device memory; no allocations)
__device__ int   g_count [K_NODES];
__device__ int   g_rowptr[K_NODES + 1];
__device__ int   g_cursor[K_NODES];
__device__ int   g_esrc  [K_EDGES];
__device__ int   g_bsum  [128];
__device__ float g_gsum  [K_GRAPHS * K_DIM];
__device__ int   g_gcnt  [K_GRAPHS];
__device__ float g_mean  [(size_t)K_NODES * K_DIM];
__device__ float g_h1    [(size_t)K_NODES * K_DIM];
__device__ float g_h2    [(size_t)K_NODES * K_DIM];

// ---------------------------------------------------------------------------
// 0) zero the per-launch accumulators
__global__ void k_zero() {
    int i = blockIdx.x * blockDim.x + threadIdx.x;
    if (i < K_NODES)           g_count[i] = 0;
    if (i < K_GRAPHS * K_DIM)  g_gsum[i]  = 0.0f;
    if (i < K_GRAPHS)          g_gcnt[i]  = 0;
}

// 1) histogram of dst
__global__ void k_count(const int* __restrict__ dst) {
    int i = blockIdx.x * blockDim.x + threadIdx.x;
    if (i < K_EDGES) atomicAdd(&g_count[dst[i]], 1);
}

// 2a) per-1024-chunk sums
__global__ void k_reduce_chunks() {
    __shared__ int sm[256];
    int b = blockIdx.x, t = threadIdx.x;
    int base = b * 1024 + t * 4;
    int s = 0;
#pragma unroll
    for (int j = 0; j < 4; ++j) {
        int i = base + j;
        if (i < K_NODES) s += g_count[i];
    }
    sm[t] = s;
    __syncthreads();
    for (int o = 128; o > 0; o >>= 1) {
        if (t < o) sm[t] += sm[t + o];
        __syncthreads();
    }
    if (t == 0) g_bsum[b] = sm[0];
}

// 2b) scan the chunk sums (single block)
__global__ void k_scan_bsums() {
    __shared__ int sm[128];
    int t = threadIdx.x;
    int v = (t < K_NB) ? g_bsum[t] : 0;
    sm[t] = v;
    __syncthreads();
    for (int o = 1; o < 128; o <<= 1) {
        int u = (t >= o) ? sm[t - o] : 0;
        __syncthreads();
        sm[t] += u;
        __syncthreads();
    }
    if (t < K_NB) g_bsum[t] = sm[t] - v;          // exclusive
    if (t == 127) g_rowptr[K_NODES] = sm[127];    // total
}

// 2c) per-chunk exclusive scan -> rowptr, cursor
__global__ void k_scan_block() {
    __shared__ int sm[256];
    int b = blockIdx.x, t = threadIdx.x;
    int base = b * 1024 + t * 4;
    int c[4];
    int s = 0;
#pragma unroll
    for (int j = 0; j < 4; ++j) {
        int i = base + j;
        c[j] = (i < K_NODES) ? g_count[i] : 0;
        s += c[j];
    }
    sm[t] = s;
    __syncthreads();
    for (int o = 1; o < 256; o <<= 1) {
        int u = (t >= o) ? sm[t - o] : 0;
        __syncthreads();
        sm[t] += u;
        __syncthreads();
    }
    int off = g_bsum[b] + sm[t] - s;              // exclusive prefix
#pragma unroll
    for (int j = 0; j < 4; ++j) {
        int i = base + j;
        if (i < K_NODES) {
            g_rowptr[i] = off;
            g_cursor[i] = off;
        }
        off += c[j];
    }
}

// 3) bucket fill: sort edge srcs by dst
__global__ void k_fill(const int* __restrict__ src, const int* __restrict__ dst) {
    int i = blockIdx.x * blockDim.x + threadIdx.x;
    if (i < K_EDGES) {
        int p = atomicAdd(&g_cursor[dst[i]], 1);
        g_esrc[p] = src[i];
    }
}

// ---------------------------------------------------------------------------
// 4) SpMM mean: one warp per dst row, gather 512B rows, accumulate, normalize
__global__ void k_spmm_mean(const float* __restrict__ X, float* __restrict__ Y) {
    int w = (blockIdx.x * blockDim.x + threadIdx.x) >> 5;
    int lane = threadIdx.x & 31;
    if (w >= K_NODES) return;
    int e0 = g_rowptr[w], e1 = g_rowptr[w + 1];
    float ax = 0.f, ay = 0.f, az = 0.f, aw = 0.f;
    int e = e0;
    for (; e + 4 <= e1; e += 4) {
        int s0 = g_esrc[e], s1 = g_esrc[e + 1], s2 = g_esrc[e + 2], s3 = g_esrc[e + 3];
        float4 v0 = *((const float4*)(X + (size_t)s0 * K_DIM) + lane);
        float4 v1 = *((const float4*)(X + (size_t)s1 * K_DIM) + lane);
        float4 v2 = *((const float4*)(X + (size_t)s2 * K_DIM) + lane);
        float4 v3 = *((const float4*)(X + (size_t)s3 * K_DIM) + lane);
        ax += v0.x + v1.x + v2.x + v3.x;
        ay += v0.y + v1.y + v2.y + v3.y;
        az += v0.z + v1.z + v2.z + v3.z;
        aw += v0.w + v1.w + v2.w + v3.w;
    }
    for (; e < e1; ++e) {
        int s = g_esrc[e];
        float4 v = *((const float4*)(X + (size_t)s * K_DIM) + lane);
        ax += v.x; ay += v.y; az += v.z; aw += v.w;
    }
    float inv = (e1 > e0) ? 1.0f / (float)(e1 - e0) : 0.0f;
    float4 r;
    r.x = ax * inv; r.y = ay * inv; r.z = az * inv; r.w = aw * inv;
    *((float4*)(Y + (size_t)w * K_DIM) + lane) = r;
}

// ---------------------------------------------------------------------------
// 5) Fused dual GEMM:  C = A1@W1 + A2@W2 + bias  (optional ReLU)
//    M x 128, K = 128+128.  Block tile 128x128, thread tile 8x8,
//    f32x2 packed FMA (2 fp32 MACs / fma-pipe slot).
__global__ __launch_bounds__(256, 2)
void k_gemm_dual(const float* __restrict__ A1, const float* __restrict__ A2,
                 const float* __restrict__ W1, const float* __restrict__ W2,
                 const float* __restrict__ bias, float* __restrict__ C,
                 int M, int doRelu) {
    __shared__ __align__(16) float Xs[32 * 132];   // [k][row], padded
    __shared__ __align__(16) float Ws[32 * 128];   // [k][n]
    int tid = threadIdx.x;
    int tx = tid & 15, ty = tid >> 4;
    int rowBase = blockIdx.x * 128;
    int r0 = ty * 8, c0 = tx * 8;

    unsigned long long acc[8][4];
#pragma unroll
    for (int r = 0; r < 8; ++r)
#pragma unroll
        for (int j = 0; j < 4; ++j) acc[r][j] = 0ull;

    int rloc = tid >> 3;            // 0..31
    int kq   = (tid & 7) << 2;      // 0,4,...,28

#pragma unroll 1
    for (int ph = 0; ph < 2; ++ph) {
        const float* A = ph ? A2 : A1;
        const float* W = ph ? W2 : W1;
#pragma unroll 1
        for (int c4 = 0; c4 < 4; ++c4) {
            int k0 = c4 * 32;
            __syncthreads();
            // load W tile 32x128
#pragma unroll
            for (int i = 0; i < 4; ++i) {
                int lin = tid + i * 256;          // float4 index
                int kk = lin >> 5;
                int nn = (lin & 31) << 2;
                *(float4*)&Ws[kk * 128 + nn] =
                    *(const float4*)&W[(size_t)(k0 + kk) * K_DIM + nn];
            }
            // load X tile 128rows x 32k, transposed into Xs[k][row]
#pragma unroll
            for (int i = 0; i < 4; ++i) {
                int rr = rloc + i * 32;
                int grow = rowBase + rr;
                if (grow >= M) grow = M - 1;
                float4 v = *(const float4*)&A[(size_t)grow * K_DIM + k0 + kq];
                Xs[(kq + 0) * 132 + rr] = v.x;
                Xs[(kq + 1) * 132 + rr] = v.y;
                Xs[(kq + 2) * 132 + rr] = v.z;
                Xs[(kq + 3) * 132 + rr] = v.w;
            }
            __syncthreads();
#pragma unroll 8
            for (int k = 0; k < 32; ++k) {
                float4 a0 = *(const float4*)&Xs[k * 132 + r0];
                float4 a1 = *(const float4*)&Xs[k * 132 + r0 + 4];
                ulonglong2 wA = *(const ulonglong2*)&Ws[k * 128 + c0];
                ulonglong2 wB = *(const ulonglong2*)&Ws[k * 128 + c0 + 4];
                unsigned long long wv[4] = {wA.x, wA.y, wB.x, wB.y};
                float ar[8] = {a0.x, a0.y, a0.z, a0.w, a1.x, a1.y, a1.z, a1.w};
#pragma unroll
                for (int r = 0; r < 8; ++r) {
                    unsigned int au = __float_as_uint(ar[r]);
                    unsigned long long a2;
                    asm("mov.b64 %0, {%1, %2};" : "=l"(a2) : "r"(au), "r"(au));
#pragma unroll
                    for (int j = 0; j < 4; ++j)
                        asm("fma.rn.f32x2 %0, %1, %2, %0;"
                            : "+l"(acc[r][j]) : "l"(a2), "l"(wv[j]));
                }
            }
        }
    }

    // epilogue: bias (+ReLU), store
    float bv[8];
#pragma unroll
    for (int j = 0; j < 8; ++j) bv[j] = bias[c0 + j];
#pragma unroll
    for (int r = 0; r < 8; ++r) {
        int grow = rowBase + r0 + r;
        if (grow >= M) continue;
#pragma unroll
        for (int j = 0; j < 4; ++j) {
            float2 v;
            memcpy(&v, &acc[r][j], 8);
            v.x += bv[2 * j];
            v.y += bv[2 * j + 1];
            if (doRelu) {
                v.x = fmaxf(v.x, 0.0f);
                v.y = fmaxf(v.y, 0.0f);
            }
            *(float2*)&C[(size_t)grow * K_DIM + c0 + 2 * j] = v;
        }
    }
}

// ---------------------------------------------------------------------------
// 6) per-graph sums (graph_ids sorted -> segmented accumulation per block)
__global__ void k_graph_accum(const float* __restrict__ H, const int* __restrict__ gid) {
    int c = threadIdx.x;                 // 128
    int rs = blockIdx.x * 64;
    if (rs >= K_NODES) return;
    int re = rs + 64;
    if (re > K_NODES) re = K_NODES;
    int cur = gid[rs];
    float acc = 0.0f;
    int cnt = 0;
    for (int r = rs; r < re; ++r) {
        int g = gid[r];
        if (g != cur) {
            atomicAdd(&g_gsum[cur * K_DIM + c], acc);
            if (c == 0) atomicAdd(&g_gcnt[cur], cnt);
            acc = 0.0f; cnt = 0; cur = g;
        }
        acc += H[(size_t)r * K_DIM + c];
        ++cnt;
    }
    atomicAdd(&g_gsum[cur * K_DIM + c], acc);
    if (c == 0) atomicAdd(&g_gcnt[cur], cnt);
}

// 7) readout: [mean(h2)|perm] @ Wc + bc
__global__ void k_classifier(const float* __restrict__ perm,
                             const float* __restrict__ Wc,
                             const float* __restrict__ bc,
                             float* __restrict__ out) {
    int t = threadIdx.x;                 // 512
    int g = t >> 3, c = t & 7;
    int cnt = g_gcnt[g];
    float inv = 1.0f / (float)(cnt > 1 ? cnt : 1);
    float acc = bc[c];
#pragma unroll 4
    for (int k = 0; k < K_DIM; ++k)
        acc += g_gsum[g * K_DIM + k] * inv * Wc[k * K_CLS + c];
#pragma unroll 4
    for (int k = 0; k < K_DIM; ++k)
        acc += perm[g * K_DIM + k] * Wc[(K_DIM + k) * K_CLS + c];
    out[g * K_CLS + c] = acc;
}

// ---------------------------------------------------------------------------
extern "C" void kernel_launch(void* const* d_in, const int* in_sizes, int n_in,
                              void* d_out, int out_size) {
    const float* h    = (const float*)d_in[0];
    const float* perm = (const float*)d_in[1];
    const int*   src  = (const int*)  d_in[2];
    const int*   dst  = (const int*)  d_in[3];
    const int*   gid  = (const int*)  d_in[4];
    const float* W1s  = (const float*)d_in[5];
    const float* W1n  = (const float*)d_in[6];
    const float* b1   = (const float*)d_in[7];
    const float* W2s  = (const float*)d_in[8];
    const float* W2n  = (const float*)d_in[9];
    const float* b2   = (const float*)d_in[10];
    const float* Wc   = (const float*)d_in[11];
    const float* bc   = (const float*)d_in[12];
    float* out = (float*)d_out;
    (void)in_sizes; (void)n_in; (void)out_size;

    float* meanb; cudaGetSymbolAddress((void**)&meanb, g_mean);
    float* h1b;   cudaGetSymbolAddress((void**)&h1b,   g_h1);
    float* h2b;   cudaGetSymbolAddress((void**)&h2b,   g_h2);

    // CSR build
    k_zero<<<(K_NODES + 255) / 256, 256>>>();
    k_count<<<(K_EDGES + 255) / 256, 256>>>(dst);
    k_reduce_chunks<<<K_NB, 256>>>();
    k_scan_bsums<<<1, 128>>>();
    k_scan_block<<<K_NB, 256>>>();
    k_fill<<<(K_EDGES + 255) / 256, 256>>>(src, dst);

    int spmmBlocks = (K_NODES * 32 + 255) / 256;
    int gemmBlocks = (K_NODES + 127) / 128;

    // layer 1
    k_spmm_mean<<<spmmBlocks, 256>>>(h, meanb);
    k_gemm_dual<<<gemmBlocks, 256>>>(h, meanb, W1s, W1n, b1, h1b, K_NODES, 1);
    // layer 2
    k_spmm_mean<<<spmmBlocks, 256>>>(h1b, meanb);
    k_gemm_dual<<<gemmBlocks, 256>>>(h1b, meanb, W2s, W2n, b2, h2b, K_NODES, 0);
    // readout
    k_graph_accum<<<(K_NODES + 63) / 64, 128>>>(h2b, gid);
    k_classifier<<<1, 512>>>(perm, Wc, bc, out);
}